// round 1
// baseline (speedup 1.0000x reference)
#include <cuda_runtime.h>
#include <math.h>

// ---------------- scratch (static device globals; no allocation) ------------
#define MAX_N   262144
#define NBINS   65536
#define MAXCAND 4096
#define TOPK    64

__device__ float        g_alpha[MAX_N];
__device__ unsigned int g_hist[NBINS];
__device__ unsigned int g_thresh_bin;
__device__ int          g_cand_count;
__device__ float        g_cand_val[MAXCAND];
__device__ int          g_cand_idx[MAXCAND];

// monotone key: order-preserving map float -> uint
__device__ __forceinline__ unsigned int fkey(float f) {
    unsigned int b = __float_as_uint(f);
    return (b & 0x80000000u) ? ~b : (b | 0x80000000u);
}

// ---------------- kernel 0: zero scratch ------------------------------------
__global__ void zero_kernel() {
    int i = blockIdx.x * blockDim.x + threadIdx.x;
    if (i < NBINS) g_hist[i] = 0u;
    if (i == 0) g_cand_count = 0;
}

// ---------------- kernel 1: alpha = vs @ v, + histogram ---------------------
// one warp per row, D = 512 (4 x float4 per lane)
__global__ void matvec_kernel(const float* __restrict__ v,
                              const float* __restrict__ vs, int N) {
    __shared__ float sv[512];
    for (int i = threadIdx.x; i < 512; i += blockDim.x) sv[i] = v[i];
    __syncthreads();

    int warp = (blockIdx.x * blockDim.x + threadIdx.x) >> 5;
    int lane = threadIdx.x & 31;
    if (warp >= N) return;

    const float4* row = (const float4*)(vs + (size_t)warp * 512);
    const float4* vv4 = (const float4*)sv;
    float acc = 0.f;
#pragma unroll
    for (int j = 0; j < 4; j++) {
        float4 x = row[lane + 32 * j];
        float4 y = vv4[lane + 32 * j];
        acc += x.x * y.x + x.y * y.y + x.z * y.z + x.w * y.w;
    }
#pragma unroll
    for (int o = 16; o; o >>= 1) acc += __shfl_xor_sync(0xffffffffu, acc, o);

    if (lane == 0) {
        g_alpha[warp] = acc;
        atomicAdd(&g_hist[fkey(acc) >> 16], 1u);
    }
}

// ---------------- kernel 2: find threshold bin (single block, 256 thr) ------
__global__ void thresh_kernel(int K) {
    __shared__ unsigned int coarse[256];
    __shared__ unsigned int fine[256];
    if (threadIdx.x < 256) coarse[threadIdx.x] = 0u;
    __syncthreads();

    // coarse[c] = sum of bins [c*256, c*256+256)
    for (int i = threadIdx.x; i < NBINS; i += blockDim.x) {
        unsigned int h = g_hist[i];
        if (h) atomicAdd(&coarse[i >> 8], h);
    }
    __syncthreads();

    __shared__ int s_chunk;
    __shared__ unsigned int s_above;
    if (threadIdx.x == 0) {
        unsigned int cum = 0;
        int c = 0;
        for (c = 255; c >= 0; c--) {
            if (cum + coarse[c] >= (unsigned int)K) break;
            cum += coarse[c];
        }
        if (c < 0) c = 0;
        s_chunk = c;
        s_above = cum;
    }
    __syncthreads();

    int c = s_chunk;
    for (int i = threadIdx.x; i < 256; i += blockDim.x)
        fine[i] = g_hist[c * 256 + i];
    __syncthreads();

    if (threadIdx.x == 0) {
        unsigned int cum = s_above;
        int b = 0;
        for (b = 255; b >= 0; b--) {
            cum += fine[b];
            if (cum >= (unsigned int)K) break;
        }
        if (b < 0) b = 0;
        g_thresh_bin = (unsigned int)(c * 256 + b);
    }
}

// ---------------- kernel 3: collect candidates ------------------------------
__global__ void collect_kernel(int N) {
    int i = blockIdx.x * blockDim.x + threadIdx.x;
    if (i >= N) return;
    unsigned int tb = g_thresh_bin;
    float a = g_alpha[i];
    if ((fkey(a) >> 16) >= tb) {
        int p = atomicAdd(&g_cand_count, 1);
        if (p < MAXCAND) { g_cand_val[p] = a; g_cand_idx[p] = i; }
    }
}

// ---------------- kernel 4: exact top-K + softmax + weighted sum ------------
__global__ void finalize_kernel(const float* __restrict__ scores,
                                float* __restrict__ out, int K) {
    __shared__ float sval[MAXCAND];
    __shared__ int   sidx[MAXCAND];
    __shared__ float rv[256];
    __shared__ int   ri[256];
    __shared__ float topv[TOPK];
    __shared__ int   topi[TOPK];

    int C = g_cand_count;
    if (C > MAXCAND) C = MAXCAND;
    for (int i = threadIdx.x; i < C; i += blockDim.x) {
        sval[i] = g_cand_val[i];
        sidx[i] = g_cand_idx[i];
    }
    __syncthreads();

    // K sequential argmax passes over C candidates (C is small, ~64..300)
    for (int k = 0; k < K; k++) {
        float best = -INFINITY; int bi = -1;
        for (int i = threadIdx.x; i < C; i += blockDim.x) {
            float s = sval[i];
            if (s > best) { best = s; bi = i; }
        }
        rv[threadIdx.x] = best; ri[threadIdx.x] = bi;
        __syncthreads();
        for (int s = 128; s; s >>= 1) {
            if (threadIdx.x < s) {
                if (rv[threadIdx.x + s] > rv[threadIdx.x]) {
                    rv[threadIdx.x] = rv[threadIdx.x + s];
                    ri[threadIdx.x] = ri[threadIdx.x + s];
                }
            }
            __syncthreads();
        }
        if (threadIdx.x == 0) {
            int b = ri[0];
            topv[k] = rv[0];
            topi[k] = (b >= 0) ? sidx[b] : 0;
            if (b >= 0) sval[b] = -INFINITY;
        }
        __syncthreads();
    }

    // softmax over topv + weighted sum of scores (threads 0..63)
    __shared__ float red[64];
    if (threadIdx.x < TOPK) {
        float vv = topv[threadIdx.x];
        red[threadIdx.x] = vv;
        __syncwarp();
        // block-of-64 max via shared (2 warps) — use simple tree with sync
    }
    __syncthreads();
    if (threadIdx.x == 0) {
        float m = -INFINITY;
        for (int k = 0; k < K; k++) m = fmaxf(m, topv[k]);
        float se = 0.f;
        float acc = 0.f;
        float e[TOPK];
#pragma unroll 8
        for (int k = 0; k < K; k++) { e[k] = __expf(topv[k] - m); se += e[k]; }
        float inv = 1.0f / se;
#pragma unroll 8
        for (int k = 0; k < K; k++) acc += e[k] * inv * scores[topi[k]];
        out[0] = acc;
    }
}

// ---------------- launch --------------------------------------------------
extern "C" void kernel_launch(void* const* d_in, const int* in_sizes, int n_in,
                              void* d_out, int out_size) {
    const float* v      = (const float*)d_in[0];
    const float* vs     = (const float*)d_in[1];
    const float* scores = (const float*)d_in[2];
    float* out = (float*)d_out;
    int N = in_sizes[2];           // 200000
    (void)n_in; (void)out_size;

    zero_kernel<<<(NBINS + 255) / 256, 256>>>();

    int warps_per_block = 8;                       // 256 threads
    int blocks = (N + warps_per_block - 1) / warps_per_block;
    matvec_kernel<<<blocks, 256>>>(v, vs, N);

    thresh_kernel<<<1, 256>>>(TOPK);

    collect_kernel<<<(N + 255) / 256, 256>>>(N);

    finalize_kernel<<<1, 256>>>(scores, out, TOPK);
}

// round 2
// speedup vs baseline: 1.3464x; 1.3464x over previous
#include <cuda_runtime.h>
#include <math.h>

#define NBINS   65536
#define NCOARSE 256
#define MAXCAND 4096
#define TOPK    64
#define MAX_N   262144

__device__ unsigned int g_hist[NBINS];
__device__ unsigned int g_coarse[NCOARSE];
__device__ float        g_alpha[MAX_N];
__device__ unsigned int g_thresh_bin;
__device__ int          g_cand_count;
__device__ float        g_cand_val[MAXCAND];
__device__ int          g_cand_idx[MAXCAND];
__device__ unsigned int g_done1;
__device__ unsigned int g_done2;

// order-preserving float -> uint key
__device__ __forceinline__ unsigned int fkey(float f) {
    unsigned int b = __float_as_uint(f);
    return (b & 0x80000000u) ? ~b : (b | 0x80000000u);
}

// ---------------- kernel 0: zero scratch (vectorized) -----------------------
__global__ void zero_kernel() {
    int i = blockIdx.x * blockDim.x + threadIdx.x;
    uint4 z = make_uint4(0u, 0u, 0u, 0u);
    if (i < NBINS / 4) ((uint4*)g_hist)[i] = z;
    if (i < NCOARSE) g_coarse[i] = 0u;
    if (i == 0) { g_cand_count = 0; g_done1 = 0u; g_done2 = 0u; }
}

// ---------------- kernel 1: matvec + histograms; last block finds threshold -
// one warp per row, D = 512 (4 x float4 per lane). blockDim = 256.
__global__ void matvec_kernel(const float* __restrict__ v,
                              const float* __restrict__ vs, int N) {
    __shared__ float sv[512];
    for (int i = threadIdx.x; i < 512; i += blockDim.x) sv[i] = v[i];
    __syncthreads();

    int warp = (blockIdx.x * blockDim.x + threadIdx.x) >> 5;
    int lane = threadIdx.x & 31;

    if (warp < N) {
        const float4* row = (const float4*)(vs + (size_t)warp * 512);
        const float4* vv4 = (const float4*)sv;
        float acc = 0.f;
#pragma unroll
        for (int j = 0; j < 4; j++) {
            float4 x = row[lane + 32 * j];
            float4 y = vv4[lane + 32 * j];
            acc += x.x * y.x + x.y * y.y + x.z * y.z + x.w * y.w;
        }
#pragma unroll
        for (int o = 16; o; o >>= 1) acc += __shfl_xor_sync(0xffffffffu, acc, o);

        if (lane == 0) {
            g_alpha[warp] = acc;
            unsigned int k = fkey(acc);
            atomicAdd(&g_hist[k >> 16], 1u);
            atomicAdd(&g_coarse[k >> 24], 1u);
        }
    }

    // ---- last-block threshold computation ----
    __shared__ bool isLast;
    __threadfence();
    __syncthreads();
    if (threadIdx.x == 0) {
        unsigned int p = atomicAdd(&g_done1, 1u);
        isLast = (p == gridDim.x - 1);
    }
    __syncthreads();
    if (!isLast) return;
    __threadfence();

    __shared__ unsigned int sc[NCOARSE];
    if (threadIdx.x < NCOARSE) sc[threadIdx.x] = g_coarse[threadIdx.x];
    __syncthreads();

    __shared__ int s_chunk;
    __shared__ unsigned int s_above;
    if (threadIdx.x == 0) {
        unsigned int cum = 0;
        int c;
        for (c = 255; c >= 0; c--) {
            if (cum + sc[c] >= (unsigned int)TOPK) break;
            cum += sc[c];
        }
        if (c < 0) c = 0;
        s_chunk = c;
        s_above = cum;
    }
    __syncthreads();

    __shared__ unsigned int sf[256];
    if (threadIdx.x < 256) sf[threadIdx.x] = g_hist[s_chunk * 256 + threadIdx.x];
    __syncthreads();

    if (threadIdx.x == 0) {
        unsigned int cum = s_above;
        int b;
        for (b = 255; b >= 0; b--) {
            cum += sf[b];
            if (cum >= (unsigned int)TOPK) break;
        }
        if (b < 0) b = 0;
        g_thresh_bin = (unsigned int)(s_chunk * 256 + b);
    }
}

// ---------------- kernel 2: collect candidates; last block finalizes --------
// vectorized float4 scan of alpha. blockDim = 256.
__global__ void collect_kernel(const float* __restrict__ scores,
                               float* __restrict__ out, int N) {
    unsigned int tb = g_thresh_bin;
    int n4 = N >> 2;
    int stride = gridDim.x * blockDim.x;
    for (int i = blockIdx.x * blockDim.x + threadIdx.x; i < n4; i += stride) {
        float4 a = ((const float4*)g_alpha)[i];
        int base = i << 2;
        if ((fkey(a.x) >> 16) >= tb) {
            int p = atomicAdd(&g_cand_count, 1);
            if (p < MAXCAND) { g_cand_val[p] = a.x; g_cand_idx[p] = base + 0; }
        }
        if ((fkey(a.y) >> 16) >= tb) {
            int p = atomicAdd(&g_cand_count, 1);
            if (p < MAXCAND) { g_cand_val[p] = a.y; g_cand_idx[p] = base + 1; }
        }
        if ((fkey(a.z) >> 16) >= tb) {
            int p = atomicAdd(&g_cand_count, 1);
            if (p < MAXCAND) { g_cand_val[p] = a.z; g_cand_idx[p] = base + 2; }
        }
        if ((fkey(a.w) >> 16) >= tb) {
            int p = atomicAdd(&g_cand_count, 1);
            if (p < MAXCAND) { g_cand_val[p] = a.w; g_cand_idx[p] = base + 3; }
        }
    }
    // tail (N not multiple of 4)
    if (blockIdx.x == 0 && threadIdx.x == 0) {
        for (int i = n4 << 2; i < N; i++) {
            float a = g_alpha[i];
            if ((fkey(a) >> 16) >= tb) {
                int p = atomicAdd(&g_cand_count, 1);
                if (p < MAXCAND) { g_cand_val[p] = a; g_cand_idx[p] = i; }
            }
        }
    }

    // ---- last-block finalize: rank selection + softmax + weighted sum ----
    __shared__ bool isLast;
    __threadfence();
    __syncthreads();
    if (threadIdx.x == 0) {
        unsigned int p = atomicAdd(&g_done2, 1u);
        isLast = (p == gridDim.x - 1);
    }
    __syncthreads();
    if (!isLast) return;
    __threadfence();

    __shared__ float sval[MAXCAND];
    __shared__ int   sidx[MAXCAND];
    int C = g_cand_count;
    if (C > MAXCAND) C = MAXCAND;
    for (int i = threadIdx.x; i < C; i += blockDim.x) {
        sval[i] = g_cand_val[i];
        sidx[i] = g_cand_idx[i];
    }
    __syncthreads();

    // block max (top-1 is always a candidate)
    __shared__ float rm[256];
    float m = -INFINITY;
    for (int i = threadIdx.x; i < C; i += blockDim.x) m = fmaxf(m, sval[i]);
    rm[threadIdx.x] = m;
    __syncthreads();
    for (int s = 128; s; s >>= 1) {
        if (threadIdx.x < s) rm[threadIdx.x] = fmaxf(rm[threadIdx.x], rm[threadIdx.x + s]);
        __syncthreads();
    }
    m = rm[0];

    // rank selection: keep candidates with rank < TOPK (total order via key+index)
    float se = 0.f, acc = 0.f;
    for (int i = threadIdx.x; i < C; i += blockDim.x) {
        float vi = sval[i];
        unsigned int ki = fkey(vi);
        int rank = 0;
        for (int j = 0; j < C; j++) {
            unsigned int kj = fkey(sval[j]);
            rank += (kj > ki) || (kj == ki && j < i);
        }
        if (rank < TOPK) {
            float e = __expf(vi - m);
            se += e;
            acc += e * scores[sidx[i]];
        }
    }

    // deterministic-order tree reductions of (se, acc)
    __shared__ float r1[256];
    __shared__ float r2[256];
    r1[threadIdx.x] = se;
    r2[threadIdx.x] = acc;
    __syncthreads();
    for (int s = 128; s; s >>= 1) {
        if (threadIdx.x < s) {
            r1[threadIdx.x] += r1[threadIdx.x + s];
            r2[threadIdx.x] += r2[threadIdx.x + s];
        }
        __syncthreads();
    }
    if (threadIdx.x == 0) out[0] = r2[0] / r1[0];
}

// ---------------- launch -----------------------------------------------------
extern "C" void kernel_launch(void* const* d_in, const int* in_sizes, int n_in,
                              void* d_out, int out_size) {
    const float* v      = (const float*)d_in[0];
    const float* vs     = (const float*)d_in[1];
    const float* scores = (const float*)d_in[2];
    float* out = (float*)d_out;
    int N = in_sizes[2];
    (void)n_in; (void)out_size;

    zero_kernel<<<(NBINS / 4 + 255) / 256, 256>>>();

    int blocks = (N * 32 + 255) / 256;  // one warp per row, 8 rows/block
    matvec_kernel<<<blocks, 256>>>(v, vs, N);

    int n4 = N >> 2;
    int cblocks = (n4 + 255) / 256;
    if (cblocks > 1024) cblocks = 1024;
    collect_kernel<<<cblocks, 256>>>(scores, out, N);
}